// round 7
// baseline (speedup 1.0000x reference)
#include <cuda_runtime.h>
#include <math.h>
#include <stdint.h>

#define NB 16384      // batch rows
#define ND 1024       // feature dim
#define NC 65         // centroids incl. extra (dots stride)
#define NC2 72        // padded anchor cols for mma (65..71 zero)
#define EPSV 1e-8f
#define SPLITK 32
#define KCHUNK (NB / SPLITK)   // 512
#define NLOSSBLK (NB / 8)

// ---------------- scratch ----------------
__device__ unsigned long long g_mask[NB];
__device__ int      g_counts[64];
__device__ int      g_nzero;
__device__ int      g_zrows[NB];
__device__ float    g_part[SPLITK][64 * ND];
__device__ float    g_asum[NC * ND];
__device__ uint32_t g_ancT[ND * NC2];        // transposed anchors, tf32 bits
__device__ float    g_ssp[2][NB];            // split-K row-norm partials
__device__ float    g_dotp[2][(size_t)NB * NC];
__device__ double   g_lpart[NLOSSBLK];

// ---------------- mma helpers ----------------
__device__ __forceinline__ uint32_t f2tf(float f) {
    uint32_t u; asm("cvt.rna.tf32.f32 %0, %1;" : "=r"(u) : "f"(f)); return u;
}
__device__ __forceinline__ void mma_tf32(float* d, uint32_t a0, uint32_t a1,
                                         uint32_t a2, uint32_t a3,
                                         uint32_t b0, uint32_t b1) {
    asm volatile(
        "mma.sync.aligned.m16n8k8.row.col.f32.tf32.tf32.f32 "
        "{%0,%1,%2,%3},{%4,%5,%6,%7},{%8,%9},{%0,%1,%2,%3};"
        : "+f"(d[0]), "+f"(d[1]), "+f"(d[2]), "+f"(d[3])
        : "r"(a0), "r"(a1), "r"(a2), "r"(a3), "r"(b0), "r"(b1));
}

// ---------------- init ----------------
__global__ void kInit() {
    if (threadIdx.x < 64) g_counts[threadIdx.x] = 0;
    if (threadIdx.x == 0) g_nzero = 0;
}

// ---------------- masks + counts + inline layout detection (warp per row) ----------
// Detection: scan 512 int32 words at r0*64 (in-bounds for BOTH layouts). If the
// buffer is int32, odd words are 256 iid 0/1 labels -> some nonzero w.p. 1-2^-256.
// If int64 (LE, values 0/1), odd words are high halves -> all zero.
__global__ __launch_bounds__(256) void kMask(const void* label) {
    __shared__ int s_cnt[64];
    if (threadIdx.x < 64) s_cnt[threadIdx.x] = 0;
    __syncthreads();

    int r0 = blockIdx.x * 8;
    const int* w = (const int*)label + (size_t)r0 * 64;
    int found = (w[2 * threadIdx.x + 1] != 0);
    bool is64 = (__syncthreads_or(found) == 0);

    int row  = r0 + (threadIdx.x >> 5);
    int lane = threadIdx.x & 31;

    long long v0, v1;
    if (is64) {
        const long long* p = (const long long*)label;
        v0 = p[(size_t)row * 64 + lane];
        v1 = p[(size_t)row * 64 + 32 + lane];
    } else {
        const int* p = (const int*)label;
        v0 = p[(size_t)row * 64 + lane];
        v1 = p[(size_t)row * 64 + 32 + lane];
    }
    unsigned lo = __ballot_sync(0xffffffffu, v0 != 0);
    unsigned hi = __ballot_sync(0xffffffffu, v1 != 0);
    unsigned long long m = (unsigned long long)lo | ((unsigned long long)hi << 32);

    if (lane == 0) {
        g_mask[row] = m;
        if (m == 0ULL) {
            int p = atomicAdd(&g_nzero, 1);
            g_zrows[p] = row;
        }
    }
    if ((lo >> lane) & 1u) atomicAdd(&s_cnt[lane], 1);
    if ((hi >> lane) & 1u) atomicAdd(&s_cnt[lane + 32], 1);
    __syncthreads();
    if (threadIdx.x < 64) atomicAdd(&g_counts[threadIdx.x], s_cnt[threadIdx.x]);
}

// ======== GEMM1 (tf32 mma): part[ks] = labT(64 x 512) @ x(512 x 64cols) ===========
__global__ __launch_bounds__(256) void kGemm1(const float* __restrict__ x) {
    int bx  = blockIdx.x;          // 0..15 : 64-col tile
    int ks  = blockIdx.y;          // 0..31 : K slice
    int tid = threadIdx.x;
    int warp = tid >> 5, lane = tid & 31;
    int mw = warp & 3;             // m base mw*16
    int nw = warp >> 2;            // n base nw*32
    int gid = lane >> 2, tig = lane & 3;

    __shared__ __align__(16) uint32_t s_b[32][72];   // 72 % 32 == 8 -> conflict-free frags
    __shared__ unsigned long long s_m[32];

    float acc[4][4] = {};
    int kbase = ks * KCHUNK;
    const float* xb = x + (size_t)kbase * ND + bx * 64;

    int r0 = tid >> 4, c0 = (tid & 15) << 2;
    int r1 = (tid + 256) >> 4, c1 = ((tid + 256) & 15) << 2;

    float4 v0 = *(const float4*)&xb[(size_t)r0 * ND + c0];
    float4 v1 = *(const float4*)&xb[(size_t)r1 * ND + c1];
    unsigned long long mv = (tid < 32) ? g_mask[kbase + tid] : 0ULL;

    const int NT = KCHUNK / 32;    // 16
    for (int t = 0; t < NT; t++) {
        __syncthreads();
        *(uint4*)&s_b[r0][c0] = make_uint4(f2tf(v0.x), f2tf(v0.y), f2tf(v0.z), f2tf(v0.w));
        *(uint4*)&s_b[r1][c1] = make_uint4(f2tf(v1.x), f2tf(v1.y), f2tf(v1.z), f2tf(v1.w));
        if (tid < 32) s_m[tid] = mv;
        __syncthreads();
        if (t + 1 < NT) {
            const float* xn = xb + (size_t)(t + 1) * 32 * ND;
            v0 = *(const float4*)&xn[(size_t)r0 * ND + c0];
            v1 = *(const float4*)&xn[(size_t)r1 * ND + c1];
            mv = (tid < 32) ? g_mask[kbase + (t + 1) * 32 + tid] : 0ULL;
        }
#pragma unroll
        for (int kk = 0; kk < 4; kk++) {
            unsigned long long mlo = s_m[kk * 8 + tig];
            unsigned long long mhi = s_m[kk * 8 + tig + 4];
            int mb = mw * 16 + gid;
            uint32_t a0 = ((mlo >> mb)       & 1ULL) ? 0x3F800000u : 0u;
            uint32_t a1 = ((mlo >> (mb + 8)) & 1ULL) ? 0x3F800000u : 0u;
            uint32_t a2 = ((mhi >> mb)       & 1ULL) ? 0x3F800000u : 0u;
            uint32_t a3 = ((mhi >> (mb + 8)) & 1ULL) ? 0x3F800000u : 0u;
#pragma unroll
            for (int j = 0; j < 4; j++) {
                uint32_t b0 = s_b[kk * 8 + tig][nw * 32 + j * 8 + gid];
                uint32_t b1 = s_b[kk * 8 + tig + 4][nw * 32 + j * 8 + gid];
                mma_tf32(acc[j], a0, a1, a2, a3, b0, b1);
            }
        }
    }
    int mg = mw * 16 + gid;
#pragma unroll
    for (int j = 0; j < 4; j++) {
        int n = bx * 64 + nw * 32 + j * 8 + tig * 2;
        g_part[ks][mg * ND + n]           = acc[j][0];
        g_part[ks][mg * ND + n + 1]       = acc[j][1];
        g_part[ks][(mg + 8) * ND + n]     = acc[j][2];
        g_part[ks][(mg + 8) * ND + n + 1] = acc[j][3];
    }
}

// -------- reduce split-K partials + extra centroid, fused (deterministic) ----------
__global__ void kRx(const float* __restrict__ x) {
    int gidx = blockIdx.x * blockDim.x + threadIdx.x;
    if (gidx < 64 * ND) {
        float s = 0.0f;
#pragma unroll
        for (int p = 0; p < SPLITK; p++) s += g_part[p][gidx];
        g_asum[gidx] = s;
    } else if (gidx < 65 * ND) {
        int d = gidx - 64 * ND;
        int nz = g_nzero;
        float s = 0.0f;
        for (int j = 0; j < nz; j++) s += x[(size_t)g_zrows[j] * ND + d];
        g_asum[64 * ND + d] = s;
    }
}

// ---- anchors: ancT[d][c] = tf32( asum[c][d] / max(||asum_c||, eps*max(cnt,1)) ) ----
__global__ __launch_bounds__(256) void kNormAnc() {
    int c = blockIdx.x;   // 0..71
    if (c >= NC) {
        for (int d = threadIdx.x; d < ND; d += 256) g_ancT[d * NC2 + c] = 0u;
        return;
    }
    __shared__ float red[256];
    __shared__ float s_scale;
    const float* row = &g_asum[c * ND];
    float s = 0.0f;
    for (int d = threadIdx.x; d < ND; d += 256) { float v = row[d]; s += v * v; }
    red[threadIdx.x] = s;
    __syncthreads();
    for (int o = 128; o > 0; o >>= 1) {
        if (threadIdx.x < o) red[threadIdx.x] += red[threadIdx.x + o];
        __syncthreads();
    }
    if (threadIdx.x == 0) {
        int cnt = (c < 64) ? g_counts[c] : g_nzero;
        float cf = (float)(cnt > 1 ? cnt : 1);
        s_scale = 1.0f / fmaxf(sqrtf(red[0]), EPSV * cf);
    }
    __syncthreads();
    float sc = s_scale;
    for (int d = threadIdx.x; d < ND; d += 256)
        g_ancT[d * NC2 + c] = f2tf(row[d] * sc);
}

// ======== GEMM2 (tf32 mma, split-K=2): dotp[ks] = x @ ancT + fused norm partials ===
__global__ __launch_bounds__(256) void kGemm2(const float* __restrict__ x) {
    int rb  = blockIdx.x * 64;
    int ks  = blockIdx.y;          // 0/1 : K half
    int tid = threadIdx.x;
    int warp = tid >> 5, lane = tid & 31;
    int mw = warp & 3;             // m base mw*16
    int nw = warp >> 2;            // n base nw*40 (frags: 5 / 4)
    int gid = lane >> 2, tig = lane & 3;

    __shared__ __align__(16) uint32_t s_x[64][36];   // a-frag LDS conflict-free
    __shared__ __align__(16) uint32_t s_a[32][72];   // b-frag LDS conflict-free
    __shared__ float s_nrm[64][8];

    float acc[5][4] = {};
    float ss0 = 0.0f, ss1 = 0.0f;
    int kb = ks * 512;
    const float* xb = x + (size_t)rb * ND + kb;

    int r0 = tid >> 3, q0 = (tid & 7) << 2;               // rows 0..31
    int r1 = 32 + r0;                                      // rows 32..63
    uint4* sa4 = (uint4*)&s_a[0][0];

    float4 v0 = *(const float4*)&xb[(size_t)r0 * ND + q0];
    float4 v1 = *(const float4*)&xb[(size_t)r1 * ND + q0];
    const uint4* at = (const uint4*)&g_ancT[(size_t)kb * NC2];
    uint4 A0 = at[tid];
    uint4 A1 = at[tid + 256];
    uint4 A2 = (tid < 64) ? at[tid + 512] : make_uint4(0, 0, 0, 0);

    const int NT = 512 / 32;       // 16
    for (int t = 0; t < NT; t++) {
        __syncthreads();
        ss0 += v0.x * v0.x + v0.y * v0.y + v0.z * v0.z + v0.w * v0.w;
        ss1 += v1.x * v1.x + v1.y * v1.y + v1.z * v1.z + v1.w * v1.w;
        *(uint4*)&s_x[r0][q0] = make_uint4(f2tf(v0.x), f2tf(v0.y), f2tf(v0.z), f2tf(v0.w));
        *(uint4*)&s_x[r1][q0] = make_uint4(f2tf(v1.x), f2tf(v1.y), f2tf(v1.z), f2tf(v1.w));
        sa4[tid]       = A0;
        sa4[tid + 256] = A1;
        if (tid < 64) sa4[tid + 512] = A2;
        __syncthreads();
        if (t + 1 < NT) {
            const float* xn = xb + (t + 1) * 32;
            v0 = *(const float4*)&xn[(size_t)r0 * ND + q0];
            v1 = *(const float4*)&xn[(size_t)r1 * ND + q0];
            const uint4* an = (const uint4*)&g_ancT[(size_t)(kb + (t + 1) * 32) * NC2];
            A0 = an[tid];
            A1 = an[tid + 256];
            if (tid < 64) A2 = an[tid + 512];
        }
#pragma unroll
        for (int kk = 0; kk < 4; kk++) {
            int mB = mw * 16 + gid;
            uint32_t a0 = s_x[mB][kk * 8 + tig];
            uint32_t a1 = s_x[mB + 8][kk * 8 + tig];
            uint32_t a2 = s_x[mB][kk * 8 + tig + 4];
            uint32_t a3 = s_x[mB + 8][kk * 8 + tig + 4];
            int nb = nw * 40;
#pragma unroll
            for (int j = 0; j < 5; j++) {
                if (nw == 0 || j < 4) {
                    uint32_t b0 = s_a[kk * 8 + tig][nb + j * 8 + gid];
                    uint32_t b1 = s_a[kk * 8 + tig + 4][nb + j * 8 + gid];
                    mma_tf32(acc[j], a0, a1, a2, a3, b0, b1);
                }
            }
        }
    }
    // fused row-norm partials (deterministic)
    __syncthreads();
    s_nrm[tid >> 3][tid & 7]        = ss0;
    s_nrm[(tid >> 3) + 32][tid & 7] = ss1;
    __syncthreads();
    if (tid < 64) {
        float s = 0.0f;
#pragma unroll
        for (int q = 0; q < 8; q++) s += s_nrm[tid][q];
        g_ssp[ks][rb + tid] = s;
    }
    // dots epilogue (cols < 65 only)
    int mg = rb + mw * 16 + gid;
#pragma unroll
    for (int j = 0; j < 5; j++) {
        if (nw == 0 || j < 4) {
            int n = nw * 40 + j * 8 + tig * 2;
            if (n < NC) {
                g_dotp[ks][(size_t)mg * NC + n]       = acc[j][0];
                g_dotp[ks][(size_t)(mg + 8) * NC + n] = acc[j][2];
            }
            if (n + 1 < NC) {
                g_dotp[ks][(size_t)mg * NC + n + 1]       = acc[j][1];
                g_dotp[ks][(size_t)(mg + 8) * NC + n + 1] = acc[j][3];
            }
        }
    }
}

// ---- loss: combine split-K dots/norms, lse + positive-pair sum, det. partials -----
__global__ __launch_bounds__(256) void kLoss(const float* __restrict__ wp,
                                             const float* __restrict__ bp) {
    __shared__ int s_act[NC];
    __shared__ double s_red[8];
    if (threadIdx.x < NC) {
        int cnt = (threadIdx.x < 64) ? g_counts[threadIdx.x] : g_nzero;
        s_act[threadIdx.x] = cnt > 0;
    }
    __syncthreads();

    int warp = threadIdx.x >> 5;
    int row  = blockIdx.x * 8 + warp;
    int lane = threadIdx.x & 31;
    float w = *wp, b = *bp;

    unsigned long long m = g_mask[row];
    float inv = 1.0f / fmaxf(sqrtf(g_ssp[0][row] + g_ssp[1][row]), EPSV);
    const float* d0 = &g_dotp[0][(size_t)row * NC];
    const float* d1 = &g_dotp[1][(size_t)row * NC];

    float l0 = s_act[lane]      ? fmaf(w * (d0[lane] + d1[lane]), inv, b) : -INFINITY;
    float l1 = s_act[lane + 32] ? fmaf(w * (d0[lane + 32] + d1[lane + 32]), inv, b) : -INFINITY;
    float l2 = (lane == 0 && s_act[64]) ? fmaf(w * (d0[64] + d1[64]), inv, b) : -INFINITY;

    float mx = fmaxf(fmaxf(l0, l1), l2);
#pragma unroll
    for (int o = 16; o; o >>= 1) mx = fmaxf(mx, __shfl_xor_sync(0xffffffffu, mx, o));

    float se = expf(l0 - mx) + expf(l1 - mx) + expf(l2 - mx);
#pragma unroll
    for (int o = 16; o; o >>= 1) se += __shfl_xor_sync(0xffffffffu, se, o);
    float lse = mx + logf(se);

    float ps = 0.0f;
    if ((m >> lane) & 1ULL)        ps += l0;
    if ((m >> (lane + 32)) & 1ULL) ps += l1;
    if (lane == 0 && m == 0ULL)    ps += l2;
#pragma unroll
    for (int o = 16; o; o >>= 1) ps += __shfl_xor_sync(0xffffffffu, ps, o);

    if (lane == 0) {
        int npos = m ? __popcll(m) : 1;
        s_red[warp] = (double)npos * (double)lse - (double)ps;
    }
    __syncthreads();
    if (threadIdx.x == 0) {
        double s = 0.0;
#pragma unroll
        for (int i = 0; i < 8; i++) s += s_red[i];
        g_lpart[blockIdx.x] = s;
    }
}

// ---------------- finalize ----------------
__global__ __launch_bounds__(256) void kFinal(float* out) {
    __shared__ double red[256];
    double s = 0.0;
    for (int i = threadIdx.x; i < NLOSSBLK; i += 256) s += g_lpart[i];
    red[threadIdx.x] = s;
    __syncthreads();
    for (int o = 128; o > 0; o >>= 1) {
        if (threadIdx.x < o) red[threadIdx.x] += red[threadIdx.x + o];
        __syncthreads();
    }
    if (threadIdx.x == 0) {
        long long np = 0;
        for (int c = 0; c < 64; c++) np += g_counts[c];
        np += g_nzero;
        out[0] = (float)(red[0] / (double)np);
    }
}

// ---------------- launch ----------------
extern "C" void kernel_launch(void* const* d_in, const int* in_sizes, int n_in,
                              void* d_out, int out_size) {
    const float* x     = (const float*)d_in[0];
    const void*  label = d_in[1];
    const float* wp    = (const float*)d_in[2];
    const float* bp    = (const float*)d_in[3];
    float* out = (float*)d_out;

    kInit<<<1, 256>>>();
    kMask<<<NB / 8, 256>>>(label);
    {
        dim3 g(ND / 64, SPLITK);
        kGemm1<<<g, 256>>>(x);
    }
    kRx<<<(65 * ND) / 256, 256>>>(x);
    kNormAnc<<<NC2, 256>>>();
    {
        dim3 g(NB / 64, 2);
        kGemm2<<<g, 256>>>(x);
    }
    kLoss<<<NLOSSBLK, 256>>>(wp, bp);
    kFinal<<<1, 256>>>(out);
}

// round 8
// speedup vs baseline: 1.6288x; 1.6288x over previous
#include <cuda_runtime.h>
#include <math.h>
#include <stdint.h>

#define NB 16384      // batch rows
#define ND 1024       // feature dim
#define NC 65         // centroids incl. extra
#define NC2 72        // padded anchor cols for mma (65..71 zero)
#define EPSV 1e-8f
#define SPLITK 32
#define KCHUNK (NB / SPLITK)   // 512
#define NBLK2 (NB / 64)        // 256 fused gemm2+loss blocks

// ---------------- scratch ----------------
__device__ unsigned long long g_mask[NB];
__device__ int      g_counts[64];
__device__ int      g_nzero;
__device__ int      g_zrows[NB];
__device__ float    g_part[SPLITK][64 * ND];
__device__ uint32_t g_ancT[ND * NC2];        // transposed anchors, tf32 bits
__device__ double   g_lpart[NBLK2];

// ---------------- mma helpers ----------------
__device__ __forceinline__ uint32_t f2tf(float f) {
    uint32_t u; asm("cvt.rna.tf32.f32 %0, %1;" : "=r"(u) : "f"(f)); return u;
}
__device__ __forceinline__ void mma_tf32(float* d, uint32_t a0, uint32_t a1,
                                         uint32_t a2, uint32_t a3,
                                         uint32_t b0, uint32_t b1) {
    asm volatile(
        "mma.sync.aligned.m16n8k8.row.col.f32.tf32.tf32.f32 "
        "{%0,%1,%2,%3},{%4,%5,%6,%7},{%8,%9},{%0,%1,%2,%3};"
        : "+f"(d[0]), "+f"(d[1]), "+f"(d[2]), "+f"(d[3])
        : "r"(a0), "r"(a1), "r"(a2), "r"(a3), "r"(b0), "r"(b1));
}

// ---------------- init ----------------
__global__ void kInit() {
    if (threadIdx.x < 64) g_counts[threadIdx.x] = 0;
    if (threadIdx.x == 0) g_nzero = 0;
}

// ------- masks + counts + inline label-width detection (warp per row) -------
__global__ __launch_bounds__(256) void kMask(const void* label) {
    __shared__ int s_cnt[64];
    if (threadIdx.x < 64) s_cnt[threadIdx.x] = 0;
    __syncthreads();

    int r0 = blockIdx.x * 8;
    const int* w = (const int*)label + (size_t)r0 * 64;
    int found = (w[2 * threadIdx.x + 1] != 0);
    bool is64 = (__syncthreads_or(found) == 0);

    int row  = r0 + (threadIdx.x >> 5);
    int lane = threadIdx.x & 31;

    long long v0, v1;
    if (is64) {
        const long long* p = (const long long*)label;
        v0 = p[(size_t)row * 64 + lane];
        v1 = p[(size_t)row * 64 + 32 + lane];
    } else {
        const int* p = (const int*)label;
        v0 = p[(size_t)row * 64 + lane];
        v1 = p[(size_t)row * 64 + 32 + lane];
    }
    unsigned lo = __ballot_sync(0xffffffffu, v0 != 0);
    unsigned hi = __ballot_sync(0xffffffffu, v1 != 0);
    unsigned long long m = (unsigned long long)lo | ((unsigned long long)hi << 32);

    if (lane == 0) {
        g_mask[row] = m;
        if (m == 0ULL) {
            int p = atomicAdd(&g_nzero, 1);
            g_zrows[p] = row;
        }
    }
    if ((lo >> lane) & 1u) atomicAdd(&s_cnt[lane], 1);
    if ((hi >> lane) & 1u) atomicAdd(&s_cnt[lane + 32], 1);
    __syncthreads();
    if (threadIdx.x < 64) atomicAdd(&g_counts[threadIdx.x], s_cnt[threadIdx.x]);
}

// ======== GEMM1 (tf32 mma): part[ks] = labT(64 x 512) @ x(512 x 64cols) ===========
__global__ __launch_bounds__(256) void kGemm1(const float* __restrict__ x) {
    int bx  = blockIdx.x;          // 0..15 : 64-col tile
    int ks  = blockIdx.y;          // 0..31 : K slice
    int tid = threadIdx.x;
    int warp = tid >> 5, lane = tid & 31;
    int mw = warp & 3, nw = warp >> 2;
    int gid = lane >> 2, tig = lane & 3;

    __shared__ __align__(16) uint32_t s_b[32][72];
    __shared__ unsigned long long s_m[32];

    float acc[4][4] = {};
    int kbase = ks * KCHUNK;
    const float* xb = x + (size_t)kbase * ND + bx * 64;

    int r0 = tid >> 4, c0 = (tid & 15) << 2;
    int r1 = (tid + 256) >> 4, c1 = ((tid + 256) & 15) << 2;

    float4 v0 = *(const float4*)&xb[(size_t)r0 * ND + c0];
    float4 v1 = *(const float4*)&xb[(size_t)r1 * ND + c1];
    unsigned long long mv = (tid < 32) ? g_mask[kbase + tid] : 0ULL;

    const int NT = KCHUNK / 32;    // 16
    for (int t = 0; t < NT; t++) {
        __syncthreads();
        *(uint4*)&s_b[r0][c0] = make_uint4(f2tf(v0.x), f2tf(v0.y), f2tf(v0.z), f2tf(v0.w));
        *(uint4*)&s_b[r1][c1] = make_uint4(f2tf(v1.x), f2tf(v1.y), f2tf(v1.z), f2tf(v1.w));
        if (tid < 32) s_m[tid] = mv;
        __syncthreads();
        if (t + 1 < NT) {
            const float* xn = xb + (size_t)(t + 1) * 32 * ND;
            v0 = *(const float4*)&xn[(size_t)r0 * ND + c0];
            v1 = *(const float4*)&xn[(size_t)r1 * ND + c1];
            mv = (tid < 32) ? g_mask[kbase + (t + 1) * 32 + tid] : 0ULL;
        }
#pragma unroll
        for (int kk = 0; kk < 4; kk++) {
            unsigned long long mlo = s_m[kk * 8 + tig];
            unsigned long long mhi = s_m[kk * 8 + tig + 4];
            int mb = mw * 16 + gid;
            uint32_t a0 = ((mlo >> mb)       & 1ULL) ? 0x3F800000u : 0u;
            uint32_t a1 = ((mlo >> (mb + 8)) & 1ULL) ? 0x3F800000u : 0u;
            uint32_t a2 = ((mhi >> mb)       & 1ULL) ? 0x3F800000u : 0u;
            uint32_t a3 = ((mhi >> (mb + 8)) & 1ULL) ? 0x3F800000u : 0u;
#pragma unroll
            for (int j = 0; j < 4; j++) {
                uint32_t b0 = s_b[kk * 8 + tig][nw * 32 + j * 8 + gid];
                uint32_t b1 = s_b[kk * 8 + tig + 4][nw * 32 + j * 8 + gid];
                mma_tf32(acc[j], a0, a1, a2, a3, b0, b1);
            }
        }
    }
    int mg = mw * 16 + gid;
#pragma unroll
    for (int j = 0; j < 4; j++) {
        int n = bx * 64 + nw * 32 + j * 8 + tig * 2;
        g_part[ks][mg * ND + n]           = acc[j][0];
        g_part[ks][mg * ND + n + 1]       = acc[j][1];
        g_part[ks][(mg + 8) * ND + n]     = acc[j][2];
        g_part[ks][(mg + 8) * ND + n + 1] = acc[j][3];
    }
}

// ==== fused: reduce split-K partials (+extra centroid) -> norm -> ancT (tf32) ====
// One block per centroid c (0..71). Coalesced 4KB-row reads of g_part.
__global__ __launch_bounds__(256) void kRxNorm(const float* __restrict__ x) {
    int c = blockIdx.x;
    if (c >= NC) {
        for (int d = threadIdx.x; d < ND; d += 256) g_ancT[d * NC2 + c] = 0u;
        return;
    }
    __shared__ float s_row[ND];
    __shared__ float red[256];
    __shared__ float s_scale;

    if (c < 64) {
        for (int d = threadIdx.x; d < ND; d += 256) {
            float s = 0.0f;
#pragma unroll
            for (int p = 0; p < SPLITK; p++) s += g_part[p][c * ND + d];
            s_row[d] = s;
        }
    } else {
        int nz = g_nzero;
        for (int d = threadIdx.x; d < ND; d += 256) {
            float s = 0.0f;
            for (int j = 0; j < nz; j++) s += x[(size_t)g_zrows[j] * ND + d];
            s_row[d] = s;
        }
    }
    __syncthreads();
    float s = 0.0f;
    for (int d = threadIdx.x; d < ND; d += 256) { float v = s_row[d]; s += v * v; }
    red[threadIdx.x] = s;
    __syncthreads();
    for (int o = 128; o > 0; o >>= 1) {
        if (threadIdx.x < o) red[threadIdx.x] += red[threadIdx.x + o];
        __syncthreads();
    }
    if (threadIdx.x == 0) {
        int cnt = (c < 64) ? g_counts[c] : g_nzero;
        float cf = (float)(cnt > 1 ? cnt : 1);
        s_scale = 1.0f / fmaxf(sqrtf(red[0]), EPSV * cf);
    }
    __syncthreads();
    float sc = s_scale;
    for (int d = threadIdx.x; d < ND; d += 256)
        g_ancT[d * NC2 + c] = f2tf(s_row[d] * sc);
}

// ==== fused GEMM2 + loss: 64 rows/block, full K=1024, dots stay in smem =========
__global__ __launch_bounds__(256) void kGemm2Loss(const float* __restrict__ x,
                                                  const float* __restrict__ wp,
                                                  const float* __restrict__ bp) {
    int rb  = blockIdx.x * 64;
    int tid = threadIdx.x;
    int warp = tid >> 5, lane = tid & 31;
    int mw = warp & 3, nw = warp >> 2;
    int gid = lane >> 2, tig = lane & 3;

    __shared__ __align__(16) uint32_t s_x[64][36];
    __shared__ __align__(16) uint32_t s_a[32][72];
    __shared__ float  s_dots[64][68];
    __shared__ float  s_nrm[64][8];
    __shared__ float  s_inv[64];
    __shared__ int    s_act[NC];
    __shared__ double s_red[8];

    if (tid < NC) {
        int cnt = (tid < 64) ? g_counts[tid] : g_nzero;
        s_act[tid] = cnt > 0;
    }

    float acc[5][4] = {};
    float ss0 = 0.0f, ss1 = 0.0f;
    const float* xb = x + (size_t)rb * ND;

    int r0 = tid >> 3, q0 = (tid & 7) << 2;   // rows 0..31
    int r1 = 32 + r0;                          // rows 32..63
    uint4* sa4 = (uint4*)&s_a[0][0];

    float4 v0 = *(const float4*)&xb[(size_t)r0 * ND + q0];
    float4 v1 = *(const float4*)&xb[(size_t)r1 * ND + q0];
    const uint4* at = (const uint4*)&g_ancT[0];
    uint4 A0 = at[tid];
    uint4 A1 = at[tid + 256];
    uint4 A2 = (tid < 64) ? at[tid + 512] : make_uint4(0, 0, 0, 0);

    const int NT = ND / 32;       // 32
    for (int t = 0; t < NT; t++) {
        __syncthreads();
        ss0 += v0.x * v0.x + v0.y * v0.y + v0.z * v0.z + v0.w * v0.w;
        ss1 += v1.x * v1.x + v1.y * v1.y + v1.z * v1.z + v1.w * v1.w;
        *(uint4*)&s_x[r0][q0] = make_uint4(f2tf(v0.x), f2tf(v0.y), f2tf(v0.z), f2tf(v0.w));
        *(uint4*)&s_x[r1][q0] = make_uint4(f2tf(v1.x), f2tf(v1.y), f2tf(v1.z), f2tf(v1.w));
        sa4[tid]       = A0;
        sa4[tid + 256] = A1;
        if (tid < 64) sa4[tid + 512] = A2;
        __syncthreads();
        if (t + 1 < NT) {
            const float* xn = xb + (t + 1) * 32;
            v0 = *(const float4*)&xn[(size_t)r0 * ND + q0];
            v1 = *(const float4*)&xn[(size_t)r1 * ND + q0];
            const uint4* an = (const uint4*)&g_ancT[(size_t)(t + 1) * 32 * NC2];
            A0 = an[tid];
            A1 = an[tid + 256];
            if (tid < 64) A2 = an[tid + 512];
        }
#pragma unroll
        for (int kk = 0; kk < 4; kk++) {
            int mB = mw * 16 + gid;
            uint32_t a0 = s_x[mB][kk * 8 + tig];
            uint32_t a1 = s_x[mB + 8][kk * 8 + tig];
            uint32_t a2 = s_x[mB][kk * 8 + tig + 4];
            uint32_t a3 = s_x[mB + 8][kk * 8 + tig + 4];
            int nb = nw * 40;
#pragma unroll
            for (int j = 0; j < 5; j++) {
                if (nw == 0 || j < 4) {
                    uint32_t b0 = s_a[kk * 8 + tig][nb + j * 8 + gid];
                    uint32_t b1 = s_a[kk * 8 + tig + 4][nb + j * 8 + gid];
                    mma_tf32(acc[j], a0, a1, a2, a3, b0, b1);
                }
            }
        }
    }

    // ---- deposit dots + norm partials in smem ----
    __syncthreads();
    s_nrm[tid >> 3][tid & 7]        = ss0;
    s_nrm[(tid >> 3) + 32][tid & 7] = ss1;
    int ml = mw * 16 + gid;
#pragma unroll
    for (int j = 0; j < 5; j++) {
        if (nw == 0 || j < 4) {
            int n = nw * 40 + j * 8 + tig * 2;
            if (n < NC) {
                s_dots[ml][n]     = acc[j][0];
                s_dots[ml + 8][n] = acc[j][2];
            }
            if (n + 1 < NC) {
                s_dots[ml][n + 1]     = acc[j][1];
                s_dots[ml + 8][n + 1] = acc[j][3];
            }
        }
    }
    __syncthreads();
    if (tid < 64) {
        float s = 0.0f;
#pragma unroll
        for (int q = 0; q < 8; q++) s += s_nrm[tid][q];
        s_inv[tid] = 1.0f / fmaxf(sqrtf(s), EPSV);
    }
    __syncthreads();

    // ---- loss: warp w handles local rows w*8..w*8+7 ----
    float w = *wp, b = *bp;
    double dsum = 0.0;
#pragma unroll
    for (int rr = 0; rr < 8; rr++) {
        int rl = warp * 8 + rr;
        unsigned long long m = g_mask[rb + rl];
        float inv = s_inv[rl];

        float l0 = s_act[lane]      ? fmaf(w * s_dots[rl][lane],      inv, b) : -INFINITY;
        float l1 = s_act[lane + 32] ? fmaf(w * s_dots[rl][lane + 32], inv, b) : -INFINITY;
        float l2 = (lane == 0 && s_act[64]) ? fmaf(w * s_dots[rl][64], inv, b) : -INFINITY;

        float mx = fmaxf(fmaxf(l0, l1), l2);
#pragma unroll
        for (int o = 16; o; o >>= 1) mx = fmaxf(mx, __shfl_xor_sync(0xffffffffu, mx, o));

        float se = expf(l0 - mx) + expf(l1 - mx) + expf(l2 - mx);
#pragma unroll
        for (int o = 16; o; o >>= 1) se += __shfl_xor_sync(0xffffffffu, se, o);
        float lse = mx + logf(se);

        float ps = 0.0f;
        if ((m >> lane) & 1ULL)        ps += l0;
        if ((m >> (lane + 32)) & 1ULL) ps += l1;
        if (lane == 0 && m == 0ULL)    ps += l2;
#pragma unroll
        for (int o = 16; o; o >>= 1) ps += __shfl_xor_sync(0xffffffffu, ps, o);

        if (lane == 0) {
            int npos = m ? __popcll(m) : 1;
            dsum += (double)npos * (double)lse - (double)ps;
        }
    }
    if (lane == 0) s_red[warp] = dsum;
    __syncthreads();
    if (tid == 0) {
        double s = 0.0;
#pragma unroll
        for (int i = 0; i < 8; i++) s += s_red[i];
        g_lpart[blockIdx.x] = s;
    }
}

// ---------------- finalize ----------------
__global__ __launch_bounds__(256) void kFinal(float* out) {
    __shared__ double red[256];
    red[threadIdx.x] = g_lpart[threadIdx.x];
    __syncthreads();
    for (int o = 128; o > 0; o >>= 1) {
        if (threadIdx.x < o) red[threadIdx.x] += red[threadIdx.x + o];
        __syncthreads();
    }
    if (threadIdx.x == 0) {
        long long np = 0;
        for (int c = 0; c < 64; c++) np += g_counts[c];
        np += g_nzero;
        out[0] = (float)(red[0] / (double)np);
    }
}

// ---------------- launch ----------------
extern "C" void kernel_launch(void* const* d_in, const int* in_sizes, int n_in,
                              void* d_out, int out_size) {
    const float* x     = (const float*)d_in[0];
    const void*  label = d_in[1];
    const float* wp    = (const float*)d_in[2];
    const float* bp    = (const float*)d_in[3];
    float* out = (float*)d_out;

    kInit<<<1, 256>>>();
    kMask<<<NB / 8, 256>>>(label);
    {
        dim3 g(ND / 64, SPLITK);
        kGemm1<<<g, 256>>>(x);
    }
    kRxNorm<<<NC2, 256>>>(x);
    kGemm2Loss<<<NBLK2, 256>>>(x, wp, bp);
    kFinal<<<1, 256>>>(out);
}

// round 10
// speedup vs baseline: 1.6577x; 1.0178x over previous
#include <cuda_runtime.h>
#include <math.h>
#include <stdint.h>

#define NB 16384      // batch rows
#define ND 1024       // feature dim
#define NC 65         // centroids incl. extra
#define NC2 72        // padded anchor cols for mma (65..71 zero)
#define EPSV 1e-8f
#define SPLITK 16
#define KCHUNK (NB / SPLITK)   // 1024
#define NBLK2 (NB / 64)        // 256 fused gemm2+loss blocks

// ---------------- scratch ----------------
__device__ unsigned long long g_mask[NB];
__device__ int      g_counts[64];
__device__ int      g_nzero;
__device__ int      g_zrows[NB];
__device__ float    g_part[SPLITK][64 * ND];
__device__ uint32_t g_ancT[ND * NC2];        // transposed anchors, tf32 bits
__device__ double   g_lpart[NBLK2];

// ---------------- helpers ----------------
__device__ __forceinline__ uint32_t f2tf(float f) {
    uint32_t u; asm("cvt.rna.tf32.f32 %0, %1;" : "=r"(u) : "f"(f)); return u;
}
__device__ __forceinline__ void mma_tf32(float* d, uint32_t a0, uint32_t a1,
                                         uint32_t a2, uint32_t a3,
                                         uint32_t b0, uint32_t b1) {
    asm volatile(
        "mma.sync.aligned.m16n8k8.row.col.f32.tf32.tf32.f32 "
        "{%0,%1,%2,%3},{%4,%5,%6,%7},{%8,%9},{%0,%1,%2,%3};"
        : "+f"(d[0]), "+f"(d[1]), "+f"(d[2]), "+f"(d[3])
        : "r"(a0), "r"(a1), "r"(a2), "r"(a3), "r"(b0), "r"(b1));
}
__device__ __forceinline__ void cpa16(uint32_t s, const void* g) {
    asm volatile("cp.async.cg.shared.global [%0], [%1], 16;\n" :: "r"(s), "l"(g));
}
__device__ __forceinline__ void cpcommit() {
    asm volatile("cp.async.commit_group;\n" ::: "memory");
}
template<int N> __device__ __forceinline__ void cpwait() {
    asm volatile("cp.async.wait_group %0;\n" :: "n"(N) : "memory");
}

// ---------------- init ----------------
__global__ void kInit() {
    if (threadIdx.x < 64) g_counts[threadIdx.x] = 0;
    if (threadIdx.x == 0) g_nzero = 0;
}

// ------- masks + counts + inline label-width detection (warp per row) -------
__global__ __launch_bounds__(256) void kMask(const void* label) {
    __shared__ int s_cnt[64];
    if (threadIdx.x < 64) s_cnt[threadIdx.x] = 0;
    __syncthreads();

    int r0 = blockIdx.x * 8;
    const int* w = (const int*)label + (size_t)r0 * 64;
    int found = (w[2 * threadIdx.x + 1] != 0);
    bool is64 = (__syncthreads_or(found) == 0);

    int row  = r0 + (threadIdx.x >> 5);
    int lane = threadIdx.x & 31;

    long long v0, v1;
    if (is64) {
        const long long* p = (const long long*)label;
        v0 = p[(size_t)row * 64 + lane];
        v1 = p[(size_t)row * 64 + 32 + lane];
    } else {
        const int* p = (const int*)label;
        v0 = p[(size_t)row * 64 + lane];
        v1 = p[(size_t)row * 64 + 32 + lane];
    }
    unsigned lo = __ballot_sync(0xffffffffu, v0 != 0);
    unsigned hi = __ballot_sync(0xffffffffu, v1 != 0);
    unsigned long long m = (unsigned long long)lo | ((unsigned long long)hi << 32);

    if (lane == 0) {
        g_mask[row] = m;
        if (m == 0ULL) {
            int p = atomicAdd(&g_nzero, 1);
            g_zrows[p] = row;
        }
    }
    if ((lo >> lane) & 1u) atomicAdd(&s_cnt[lane], 1);
    if ((hi >> lane) & 1u) atomicAdd(&s_cnt[lane + 32], 1);
    __syncthreads();
    if (threadIdx.x < 64) atomicAdd(&g_counts[threadIdx.x], s_cnt[threadIdx.x]);
}

// ======== GEMM1 (tf32 mma, cp.async 3-stage): part[ks] = labT @ x(64 cols) ========
__global__ __launch_bounds__(256) void kGemm1(const float* __restrict__ x) {
    int bx  = blockIdx.x;          // 0..15 : 64-col tile
    int ks  = blockIdx.y;          // 0..15 : K slice (1024 rows)
    int tid = threadIdx.x;
    int warp = tid >> 5, lane = tid & 31;
    int mw = warp & 3, nw = warp >> 2;
    int gid = lane >> 2, tig = lane & 3;

    __shared__ __align__(16) uint32_t s_b[3][32][72];
    __shared__ __align__(16) unsigned long long s_m[3][32];

    uint32_t sb0 = (uint32_t)__cvta_generic_to_shared(&s_b[0][0][0]);
    uint32_t sm0 = (uint32_t)__cvta_generic_to_shared(&s_m[0][0]);

    float acc[4][4] = {};
    int kbase = ks * KCHUNK;
    const float* xb = x + (size_t)kbase * ND + bx * 64;

    const int NT = KCHUNK / 32;    // 32 tiles
    int i0 = tid * 2, i1 = i0 + 1;
    int pr0 = i0 >> 4, pc0 = (i0 & 15) << 2;
    int pr1 = i1 >> 4, pc1 = (i1 & 15) << 2;

#define G1_PRODUCE(slot, t)                                                     \
    do {                                                                        \
        const float* xs = xb + (size_t)(t) * 32 * ND;                           \
        cpa16(sb0 + (slot) * 9216 + (pr0 * 72 + pc0) * 4,                       \
              &xs[(size_t)pr0 * ND + pc0]);                                     \
        cpa16(sb0 + (slot) * 9216 + (pr1 * 72 + pc1) * 4,                       \
              &xs[(size_t)pr1 * ND + pc1]);                                     \
        if (tid < 16)                                                           \
            cpa16(sm0 + (slot) * 256 + tid * 16,                                \
                  &g_mask[kbase + (t) * 32 + tid * 2]);                         \
    } while (0)

    G1_PRODUCE(0, 0); cpcommit();
    G1_PRODUCE(1, 1); cpcommit();

    for (int t = 0; t < NT; t++) {
        if (t + 2 < NT) { int sl = (t + 2) % 3; G1_PRODUCE(sl, t + 2); }
        cpcommit();
        cpwait<2>();
        __syncthreads();
        int s = t % 3;
#pragma unroll
        for (int kk = 0; kk < 4; kk++) {
            unsigned long long mlo = s_m[s][kk * 8 + tig];
            unsigned long long mhi = s_m[s][kk * 8 + tig + 4];
            int mb = mw * 16 + gid;
            uint32_t a0 = ((mlo >> mb)       & 1ULL) ? 0x3F800000u : 0u;
            uint32_t a1 = ((mlo >> (mb + 8)) & 1ULL) ? 0x3F800000u : 0u;
            uint32_t a2 = ((mhi >> mb)       & 1ULL) ? 0x3F800000u : 0u;
            uint32_t a3 = ((mhi >> (mb + 8)) & 1ULL) ? 0x3F800000u : 0u;
#pragma unroll
            for (int j = 0; j < 4; j++) {
                uint32_t b0 = s_b[s][kk * 8 + tig][nw * 32 + j * 8 + gid];
                uint32_t b1 = s_b[s][kk * 8 + tig + 4][nw * 32 + j * 8 + gid];
                mma_tf32(acc[j], a0, a1, a2, a3, b0, b1);
            }
        }
        __syncthreads();
    }
    int mg = mw * 16 + gid;
#pragma unroll
    for (int j = 0; j < 4; j++) {
        int n = bx * 64 + nw * 32 + j * 8 + tig * 2;
        g_part[ks][mg * ND + n]           = acc[j][0];
        g_part[ks][mg * ND + n + 1]       = acc[j][1];
        g_part[ks][(mg + 8) * ND + n]     = acc[j][2];
        g_part[ks][(mg + 8) * ND + n + 1] = acc[j][3];
    }
#undef G1_PRODUCE
}

// ==== fused: reduce split-K partials (+extra centroid) -> norm -> ancT (tf32) ====
__global__ __launch_bounds__(256) void kRxNorm(const float* __restrict__ x) {
    int c = blockIdx.x;
    if (c >= NC) {
        for (int d = threadIdx.x; d < ND; d += 256) g_ancT[d * NC2 + c] = 0u;
        return;
    }
    __shared__ float s_row[ND];
    __shared__ float red[256];
    __shared__ float s_scale;

    if (c < 64) {
        for (int d = threadIdx.x; d < ND; d += 256) {
            float s = 0.0f;
#pragma unroll
            for (int p = 0; p < SPLITK; p++) s += g_part[p][c * ND + d];
            s_row[d] = s;
        }
    } else {
        int nz = g_nzero;
        for (int d = threadIdx.x; d < ND; d += 256) {
            float s = 0.0f;
            for (int j = 0; j < nz; j++) s += x[(size_t)g_zrows[j] * ND + d];
            s_row[d] = s;
        }
    }
    __syncthreads();
    float s = 0.0f;
    for (int d = threadIdx.x; d < ND; d += 256) { float v = s_row[d]; s += v * v; }
    red[threadIdx.x] = s;
    __syncthreads();
    for (int o = 128; o > 0; o >>= 1) {
        if (threadIdx.x < o) red[threadIdx.x] += red[threadIdx.x + o];
        __syncthreads();
    }
    if (threadIdx.x == 0) {
        int cnt = (c < 64) ? g_counts[c] : g_nzero;
        float cf = (float)(cnt > 1 ? cnt : 1);
        s_scale = 1.0f / fmaxf(sqrtf(red[0]), EPSV * cf);
    }
    __syncthreads();
    float sc = s_scale;
    for (int d = threadIdx.x; d < ND; d += 256)
        g_ancT[d * NC2 + c] = f2tf(s_row[d] * sc);
}

// ==== fused GEMM2 + loss (cp.async 2-stage; dots overlay anchor stages) ==========
__global__ __launch_bounds__(256) void kGemm2Loss(const float* __restrict__ x,
                                                  const float* __restrict__ wp,
                                                  const float* __restrict__ bp) {
    int rb  = blockIdx.x * 64;
    int tid = threadIdx.x;
    int warp = tid >> 5, lane = tid & 31;
    int mw = warp & 3, nw = warp >> 2;
    int gid = lane >> 2, tig = lane & 3;

    __shared__ __align__(16) uint32_t s_x[2][64][36];   // 18432 B, raw fp32 bits
    __shared__ __align__(16) uint32_t s_u[2][32][72];   // anchors; dots overlay after
    __shared__ float  s_nrm[64][4];
    __shared__ float  s_inv[64];
    __shared__ int    s_act[NC];
    __shared__ double s_red[8];

    if (tid < NC) {
        int cnt = (tid < 64) ? g_counts[tid] : g_nzero;
        s_act[tid] = cnt > 0;
    }

    uint32_t sx0 = (uint32_t)__cvta_generic_to_shared(&s_x[0][0][0]);
    uint32_t sa0 = (uint32_t)__cvta_generic_to_shared(&s_u[0][0][0]);

    float acc[5][4] = {};
    float ssl = 0.0f;
    const float* xb = x + (size_t)rb * ND;

    const int NT = ND / 32;       // 32 tiles
    int i0 = tid * 2, i1 = i0 + 1;
    int pr0 = i0 >> 3, pc0 = (i0 & 7) << 2;
    int pr1 = i1 >> 3, pc1 = (i1 & 7) << 2;
    int nrow = tid & 63, nch = tid >> 6;       // norm: row, 8-wide chunk

#define G2_PRODUCE(slot, t)                                                     \
    do {                                                                        \
        const float* xs = xb + (t) * 32;                                        \
        cpa16(sx0 + (slot) * 9216 + (pr0 * 36 + pc0) * 4,                       \
              &xs[(size_t)pr0 * ND + pc0]);                                     \
        cpa16(sx0 + (slot) * 9216 + (pr1 * 36 + pc1) * 4,                       \
              &xs[(size_t)pr1 * ND + pc1]);                                     \
        const uint4* ag = (const uint4*)&g_ancT[(size_t)(t) * 32 * NC2];        \
        cpa16(sa0 + (slot) * 9216 + tid * 16, ag + tid);                        \
        cpa16(sa0 + (slot) * 9216 + (tid + 256) * 16, ag + tid + 256);          \
        if (tid < 64)                                                           \
            cpa16(sa0 + (slot) * 9216 + (tid + 512) * 16, ag + tid + 512);      \
    } while (0)

    G2_PRODUCE(0, 0); cpcommit();

    for (int t = 0; t < NT; t++) {
        if (t + 1 < NT) { int sl = (t + 1) & 1; G2_PRODUCE(sl, t + 1); }
        cpcommit();
        cpwait<1>();
        __syncthreads();
        int s = t & 1;
        // fused row-norm partial from the exact fp32 tile
        {
            const uint4* p = (const uint4*)&s_x[s][nrow][nch * 8];
            uint4 u0 = p[0], u1 = p[1];
            float f;
            f = __uint_as_float(u0.x); ssl += f * f;
            f = __uint_as_float(u0.y); ssl += f * f;
            f = __uint_as_float(u0.z); ssl += f * f;
            f = __uint_as_float(u0.w); ssl += f * f;
            f = __uint_as_float(u1.x); ssl += f * f;
            f = __uint_as_float(u1.y); ssl += f * f;
            f = __uint_as_float(u1.z); ssl += f * f;
            f = __uint_as_float(u1.w); ssl += f * f;
        }
#pragma unroll
        for (int kk = 0; kk < 4; kk++) {
            int mB = mw * 16 + gid;
            uint32_t a0 = s_x[s][mB][kk * 8 + tig];
            uint32_t a1 = s_x[s][mB + 8][kk * 8 + tig];
            uint32_t a2 = s_x[s][mB][kk * 8 + tig + 4];
            uint32_t a3 = s_x[s][mB + 8][kk * 8 + tig + 4];
            int nb = nw * 40;
#pragma unroll
            for (int j = 0; j < 5; j++) {
                if (nw == 0 || j < 4) {
                    uint32_t b0 = s_u[s][kk * 8 + tig][nb + j * 8 + gid];
                    uint32_t b1 = s_u[s][kk * 8 + tig + 4][nb + j * 8 + gid];
                    mma_tf32(acc[j], a0, a1, a2, a3, b0, b1);
                }
            }
        }
        __syncthreads();
    }
#undef G2_PRODUCE

    // ---- deposit dots (overlay s_u) + norms ----
    float (*s_dots)[68] = (float(*)[68])&s_u[0][0][0];   // 64*68*4 = 17408 <= 18432
    s_nrm[nrow][nch] = ssl;
    int ml = mw * 16 + gid;
#pragma unroll
    for (int j = 0; j < 5; j++) {
        if (nw == 0 || j < 4) {
            int n = nw * 40 + j * 8 + tig * 2;
            if (n < NC) {
                s_dots[ml][n]     = acc[j][0];
                s_dots[ml + 8][n] = acc[j][2];
            }
            if (n + 1 < NC) {
                s_dots[ml][n + 1]     = acc[j][1];
                s_dots[ml + 8][n + 1] = acc[j][3];
            }
        }
    }
    __syncthreads();
    if (tid < 64) {
        float s = s_nrm[tid][0] + s_nrm[tid][1] + s_nrm[tid][2] + s_nrm[tid][3];
        s_inv[tid] = 1.0f / fmaxf(sqrtf(s), EPSV);
    }
    __syncthreads();

    // ---- loss: warp w handles local rows w*8..w*8+7 ----
    float w = *wp, b = *bp;
    double dsum = 0.0;
#pragma unroll
    for (int rr = 0; rr < 8; rr++) {
        int rl = warp * 8 + rr;
        unsigned long long m = g_mask[rb + rl];
        float inv = s_inv[rl];

        float l0 = s_act[lane]      ? fmaf(w * s_dots[rl][lane],      inv, b) : -INFINITY;
        float l1 = s_act[lane + 32] ? fmaf(w * s_dots[rl][lane + 32], inv, b) : -INFINITY;
        float l2 = (lane == 0 && s_act[64]) ? fmaf(w * s_dots[rl][64], inv, b) : -INFINITY;

        float mx = fmaxf(fmaxf(l0, l1), l2);
#pragma unroll
        for (int o = 16; o; o >>= 1) mx = fmaxf(mx, __shfl_xor_sync(0xffffffffu, mx, o));

        float se = expf(l0 - mx) + expf(l1 - mx) + expf(l2 - mx);
#pragma unroll
        for (int o = 16; o; o >>= 1) se += __shfl_xor_sync(0xffffffffu, se, o);
        float lse = mx + logf(se);

        float ps = 0.0f;
        if ((m >> lane) & 1ULL)        ps += l0;
        if ((m >> (lane + 32)) & 1ULL) ps += l1;
        if (lane == 0 && m == 0ULL)    ps += l2;
#pragma unroll
        for (int o = 16; o; o >>= 1) ps += __shfl_xor_sync(0xffffffffu, ps, o);

        if (lane == 0) {
            int npos = m ? __popcll(m) : 1;
            dsum += (double)npos * (double)lse - (double)ps;
        }
    }
    if (lane == 0) s_red[warp] = dsum;
    __syncthreads();
    if (tid == 0) {
        double s = 0.0;
#pragma unroll
        for (int i = 0; i < 8; i++) s += s_red[i];
        g_lpart[blockIdx.x] = s;
    }
}

// ---------------- finalize ----------------
__global__ __launch_bounds__(256) void kFinal(float* out) {
    __shared__ double red[256];
    red[threadIdx.x] = g_lpart[threadIdx.x];
    __syncthreads();
    for (int o = 128; o > 0; o >>= 1) {
        if (threadIdx.x < o) red[threadIdx.x] += red[threadIdx.x + o];
        __syncthreads();
    }
    if (threadIdx.x == 0) {
        long long np = 0;
        for (int c = 0; c < 64; c++) np += g_counts[c];
        np += g_nzero;
        out[0] = (float)(red[0] / (double)np);
    }
}

// ---------------- launch ----------------
extern "C" void kernel_launch(void* const* d_in, const int* in_sizes, int n_in,
                              void* d_out, int out_size) {
    const float* x     = (const float*)d_in[0];
    const void*  label = d_in[1];
    const float* wp    = (const float*)d_in[2];
    const float* bp    = (const float*)d_in[3];
    float* out = (float*)d_out;

    kInit<<<1, 256>>>();
    kMask<<<NB / 8, 256>>>(label);
    {
        dim3 g(ND / 64, SPLITK);
        kGemm1<<<g, 256>>>(x);
    }
    kRxNorm<<<NC2, 256>>>(x);
    kGemm2Loss<<<NBLK2, 256>>>(x, wp, bp);
    kFinal<<<1, 256>>>(out);
}